// round 6
// baseline (speedup 1.0000x reference)
#include <cuda_runtime.h>
#include <cuda_bf16.h>
#include <math.h>
#include <cstdint>

#define B_    8
#define SEQ   8192
#define DIM   512
#define HEADS 8
#define HD    64
#define FF_   2048
#define WIN   128
#define TD    512
#define NTOK  (B_*SEQ)        // 65536
#define NW    (SEQ/WIN)       // 64

// ---------------- scratch (device globals; no runtime allocation) ----------
__device__ float g_ss  [B_ * 2 * DIM];
__device__ float g_y   [(size_t)NTOK * DIM];       // x + proj(attn), fp32
// hi/lo bf16 activations
__device__ __nv_bfloat16 g_xh [(size_t)NTOK * DIM],  g_xl [(size_t)NTOK * DIM];
__device__ __nv_bfloat16 g_ah [(size_t)NTOK * DIM],  g_al [(size_t)NTOK * DIM];
__device__ __nv_bfloat16 g_fh [(size_t)NTOK * FF_],  g_fl [(size_t)NTOK * FF_];
__device__ __nv_bfloat16 g_qh [(size_t)NTOK * 3 * DIM], g_ql [(size_t)NTOK * 3 * DIM];
// weights hi/lo, transposed to [N][K] bf16 (K contiguous)
__device__ __nv_bfloat16 g_wq_h[1536 * 512],  g_wq_l[1536 * 512];
__device__ __nv_bfloat16 g_wp_h[512 * 512],   g_wp_l[512 * 512];
__device__ __nv_bfloat16 g_w1_h[2048 * 512],  g_w1_l[2048 * 512];
__device__ __nv_bfloat16 g_w2_h[512 * 2048],  g_w2_l[512 * 2048];

// ---------------- PTX helpers ----------------------------------------------
__device__ __forceinline__ uint32_t smem_u32(const void* p) {
    uint32_t a;
    asm("{ .reg .u64 t; cvta.to.shared.u64 t, %1; cvt.u32.u64 %0, t; }"
        : "=r"(a) : "l"(p));
    return a;
}
__device__ __forceinline__ void cp16(uint32_t dst, const void* src) {
    asm volatile("cp.async.cg.shared.global [%0], [%1], 16;"
                 :: "r"(dst), "l"(src) : "memory");
}
#define CP_COMMIT() asm volatile("cp.async.commit_group;" ::: "memory")
#define CP_WAIT(n)  asm volatile("cp.async.wait_group %0;" :: "n"(n) : "memory")

__device__ __forceinline__ void ldsm4(uint32_t* r, uint32_t addr) {
    asm volatile("ldmatrix.sync.aligned.m8n8.x4.shared.b16 {%0,%1,%2,%3}, [%4];"
                 : "=r"(r[0]), "=r"(r[1]), "=r"(r[2]), "=r"(r[3]) : "r"(addr));
}
__device__ __forceinline__ void ldsm4t(uint32_t* r, uint32_t addr) {
    asm volatile("ldmatrix.sync.aligned.m8n8.x4.trans.shared.b16 {%0,%1,%2,%3}, [%4];"
                 : "=r"(r[0]), "=r"(r[1]), "=r"(r[2]), "=r"(r[3]) : "r"(addr));
}
__device__ __forceinline__ void mma16816(float* d, const uint32_t* a,
                                         const uint32_t* b) {
    asm volatile(
        "mma.sync.aligned.m16n8k16.row.col.f32.bf16.bf16.f32 "
        "{%0,%1,%2,%3}, {%4,%5,%6,%7}, {%8,%9}, {%0,%1,%2,%3};"
        : "+f"(d[0]), "+f"(d[1]), "+f"(d[2]), "+f"(d[3])
        : "r"(a[0]), "r"(a[1]), "r"(a[2]), "r"(a[3]), "r"(b[0]), "r"(b[1]));
}
__device__ __forceinline__ uint32_t swz(uint32_t r, uint32_t c16) {
    return (r << 7) + ((c16 ^ (r & 7)) << 4);
}
__device__ __forceinline__ void split_hl(float v, __nv_bfloat16& h, __nv_bfloat16& l) {
    h = __float2bfloat16(v);
    l = __float2bfloat16(v - __bfloat162float(h));
}
__device__ __forceinline__ uint32_t pack_bf2(__nv_bfloat16 a, __nv_bfloat16 b) {
    __nv_bfloat162 p = __halves2bfloat162(a, b);
    return *reinterpret_cast<uint32_t*>(&p);
}

// ---------------- kernel 0: coalesced weight transpose + hi/lo split -------
__global__ void wprep_kernel(const float* __restrict__ W,
                             __nv_bfloat16* __restrict__ oh,
                             __nv_bfloat16* __restrict__ ol, int K, int N) {
    __shared__ float tile[32][33];
    int bx = blockIdx.x * 32, by = blockIdx.y * 32;
    int tx = threadIdx.x, ty = threadIdx.y;
    #pragma unroll
    for (int i = 0; i < 4; i++) {
        int k = by + ty + i * 8;
        tile[ty + i * 8][tx] = W[(size_t)k * N + bx + tx];
    }
    __syncthreads();
    #pragma unroll
    for (int i = 0; i < 4; i++) {
        int n = bx + ty + i * 8;
        int k = by + tx;
        float v = tile[tx][ty + i * 8];
        __nv_bfloat16 h, l; split_hl(v, h, l);
        oh[(size_t)n * K + k] = h;
        ol[(size_t)n * K + k] = l;
    }
}

// ---------------- kernel 1: ss = silu(t_emb) @ time_w + time_b -------------
__global__ void time_mlp_kernel(const float* __restrict__ te,
                                const float* __restrict__ tw,
                                const float* __restrict__ tb) {
    __shared__ float st[TD];
    int b = blockIdx.y;
    for (int k = threadIdx.x; k < TD; k += blockDim.x) {
        float v = te[b * TD + k];
        st[k] = v / (1.f + __expf(-v));
    }
    __syncthreads();
    int j = blockIdx.x * blockDim.x + threadIdx.x;
    float acc = tb[j];
    for (int k = 0; k < TD; k++)
        acc = fmaf(st[k], tw[k * (2 * DIM) + j], acc);
    g_ss[b * 2 * DIM + j] = acc;
}

// ---------------- kernel 2: LayerNorm -> bf16 hi/lo ------------------------
template <int MOD>
__global__ void ln_kernel(const float* __restrict__ x,
                          const float* __restrict__ gam,
                          const float* __restrict__ bet,
                          __nv_bfloat16* __restrict__ oh,
                          __nv_bfloat16* __restrict__ ol) {
    int row  = blockIdx.x;
    int t    = threadIdx.x;
    int lane = t & 31, wid = t >> 5;
    float4 xv = ((const float4*)(x + (size_t)row * DIM))[t];
    float s  = xv.x + xv.y + xv.z + xv.w;
    float s2 = fmaf(xv.x, xv.x, fmaf(xv.y, xv.y, fmaf(xv.z, xv.z, xv.w * xv.w)));
    #pragma unroll
    for (int o = 16; o > 0; o >>= 1) {
        s  += __shfl_xor_sync(0xffffffffu, s,  o);
        s2 += __shfl_xor_sync(0xffffffffu, s2, o);
    }
    __shared__ float red[8];
    if (lane == 0) { red[wid] = s; red[4 + wid] = s2; }
    __syncthreads();
    s  = red[0] + red[1] + red[2] + red[3];
    s2 = red[4] + red[5] + red[6] + red[7];
    float mu   = s * (1.f / DIM);
    float var  = s2 * (1.f / DIM) - mu * mu;
    float rstd = rsqrtf(var + 1e-5f);

    float4 gg = ((const float4*)gam)[t];
    float4 bb = ((const float4*)bet)[t];
    float o4[4];
    o4[0] = (xv.x - mu) * rstd * gg.x + bb.x;
    o4[1] = (xv.y - mu) * rstd * gg.y + bb.y;
    o4[2] = (xv.z - mu) * rstd * gg.z + bb.z;
    o4[3] = (xv.w - mu) * rstd * gg.w + bb.w;
    if (MOD) {
        int b = row >> 13;
        float4 sc = ((const float4*)(g_ss + b * 2 * DIM))[t];
        float4 sh = ((const float4*)(g_ss + b * 2 * DIM + DIM))[t];
        o4[0] = o4[0] * (1.f + sc.x) + sh.x;
        o4[1] = o4[1] * (1.f + sc.y) + sh.y;
        o4[2] = o4[2] * (1.f + sc.z) + sh.z;
        o4[3] = o4[3] * (1.f + sc.w) + sh.w;
    }
    __nv_bfloat16 h[4], l[4];
    #pragma unroll
    for (int i = 0; i < 4; i++) split_hl(o4[i], h[i], l[i]);
    ((uint2*)(oh + (size_t)row * DIM))[t] =
        make_uint2(pack_bf2(h[0], h[1]), pack_bf2(h[2], h[3]));
    ((uint2*)(ol + (size_t)row * DIM))[t] =
        make_uint2(pack_bf2(l[0], l[1]), pack_bf2(l[2], l[3]));
}

// ---------------- kernel 3: mma.sync bf16 GEMM, 3-stage pipeline -----------
// EPI: 0 = bias -> f32; 1 = bias+res -> f32; 2 = bias+GELU -> hi/lo;
//      3 = bias, cols<512 scaled 0.125 (Q) -> hi/lo  (QKV epilogue)
#define KSTEP 32
#define STG   32768
template <int EPI>
__global__ __launch_bounds__(256, 2)
void mma_gemm(const __nv_bfloat16* __restrict__ Ah,
              const __nv_bfloat16* __restrict__ Al,
              const __nv_bfloat16* __restrict__ Bh,
              const __nv_bfloat16* __restrict__ Bl,
              const float* __restrict__ bias,
              const float* __restrict__ res,
              float* __restrict__ Cf,
              __nv_bfloat16* __restrict__ Ch,
              __nv_bfloat16* __restrict__ Cl,
              int K, int N) {
    extern __shared__ char smem[];
    const uint32_t sbase = smem_u32(smem);
    const int tid = threadIdx.x, w = tid >> 5, lane = tid & 31;
    const int bm = blockIdx.y * 128, bn = blockIdx.x * 128;
    const int warpM = (w >> 2) * 64, warpN = (w & 3) * 32;
    const int T = K / KSTEP;

    const int r_ld = tid >> 3, c_ld = tid & 7;

    auto issue = [&](int t) {
        int k0 = t * KSTEP;
        uint32_t sa = sbase + (t % 3) * STG;
        uint32_t sb = sa + 16384;
        #pragma unroll
        for (int i = 0; i < 4; i++) {
            int r = r_ld + i * 32;
            const __nv_bfloat16* srcA = (c_ld < 4)
                ? Ah + (size_t)(bm + r) * K + k0 + c_ld * 8
                : Al + (size_t)(bm + r) * K + k0 + (c_ld - 4) * 8;
            cp16(sa + swz(r, c_ld), srcA);
            const __nv_bfloat16* srcB = (c_ld < 4)
                ? Bh + (size_t)(bn + r) * K + k0 + c_ld * 8
                : Bl + (size_t)(bn + r) * K + k0 + (c_ld - 4) * 8;
            cp16(sb + swz(r, c_ld), srcB);
        }
        CP_COMMIT();
    };

    float acc[4][4][4];
    #pragma unroll
    for (int i = 0; i < 4; i++)
        #pragma unroll
        for (int j = 0; j < 4; j++)
            #pragma unroll
            for (int e = 0; e < 4; e++) acc[i][j][e] = 0.f;

    const int laA_r = lane & 15, laA_h = lane >> 4;
    const int laB_r = (lane & 7) + ((lane >> 4) << 3);
    const int laB_h = (lane >> 3) & 1;

    issue(0);
    issue(1);
    for (int t = 0; t < T; t++) {
        if (t == T - 1) { CP_WAIT(0); } else { CP_WAIT(1); }
        __syncthreads();

        uint32_t sa = sbase + (t % 3) * STG;
        uint32_t sb = sa + 16384;
        const int SA[6] = {0, 1, 0, 1, 2, 3};
        const int SB[6] = {0, 1, 2, 3, 0, 1};
        #pragma unroll
        for (int s = 0; s < 6; s++) {
            int ka = SA[s], kb = SB[s];
            uint32_t afr[4][4], bfr[2][4];
            #pragma unroll
            for (int mi = 0; mi < 4; mi++) {
                uint32_t row = warpM + mi * 16 + laA_r;
                ldsm4(afr[mi], sa + swz(row, ka * 2 + laA_h));
            }
            #pragma unroll
            for (int nj = 0; nj < 2; nj++) {
                uint32_t row = warpN + nj * 16 + laB_r;
                ldsm4(bfr[nj], sb + swz(row, kb * 2 + laB_h));
            }
            #pragma unroll
            for (int mi = 0; mi < 4; mi++)
                #pragma unroll
                for (int n8 = 0; n8 < 4; n8++)
                    mma16816(acc[mi][n8], afr[mi], &bfr[n8 >> 1][(n8 & 1) * 2]);
        }
        if (t + 2 < T) issue(t + 2);
    }

    int tr = lane >> 2, tc = (lane & 3) * 2;
    #pragma unroll
    for (int mi = 0; mi < 4; mi++) {
        #pragma unroll
        for (int half = 0; half < 2; half++) {
            int row = bm + warpM + mi * 16 + tr + half * 8;
            size_t rowoff = (size_t)row * N;
            #pragma unroll
            for (int n8 = 0; n8 < 4; n8++) {
                int col = bn + warpN + n8 * 8 + tc;
                float2 bi = *(const float2*)(bias + col);
                float ox = acc[mi][n8][half * 2 + 0] + bi.x;
                float oy = acc[mi][n8][half * 2 + 1] + bi.y;
                if (EPI == 1) {
                    float2 rr = *(const float2*)(res + rowoff + col);
                    ox += rr.x; oy += rr.y;
                }
                if (EPI == 2) {
                    ox = 0.5f * ox * (1.f + erff(ox * 0.70710678118654752f));
                    oy = 0.5f * oy * (1.f + erff(oy * 0.70710678118654752f));
                }
                if (EPI == 3) {
                    float sc = (col < 512) ? 0.125f : 1.0f;
                    ox *= sc; oy *= sc;
                }
                if (EPI == 2 || EPI == 3) {
                    __nv_bfloat16 hx, lx, hy, ly;
                    split_hl(ox, hx, lx); split_hl(oy, hy, ly);
                    *(uint32_t*)(Ch + rowoff + col) = pack_bf2(hx, hy);
                    *(uint32_t*)(Cl + rowoff + col) = pack_bf2(lx, ly);
                } else {
                    *(float2*)(Cf + rowoff + col) = make_float2(ox, oy);
                }
            }
        }
    }
}

// ---------------- kernel 4: local windowed attention via mma.sync ----------
// Inputs already bf16 hi/lo (Q pre-scaled). grid (NW, HEADS, B_), 128 thr.
__global__ __launch_bounds__(128)
void attn_mma_kernel(const __nv_bfloat16* __restrict__ qh,
                     const __nv_bfloat16* __restrict__ ql,
                     __nv_bfloat16* __restrict__ oh,
                     __nv_bfloat16* __restrict__ ol) {
    extern __shared__ char smc[];
    const uint32_t sQh = smem_u32(smc);
    const uint32_t sQl = sQh + 16384;
    const uint32_t sKh = sQh + 32768;
    const uint32_t sKl = sQh + 49152;
    const uint32_t sVh = sQh + 65536;
    const uint32_t sVl = sQh + 81920;

    const int w = blockIdx.x, h = blockIdx.y, b = blockIdx.z;
    const int tid = threadIdx.x, lane = tid & 31;
    const int warpM = (tid >> 5) * 32;

    const int laA_r = lane & 15, laA_h = lane >> 4;
    const int laB_r = (lane & 7) + ((lane >> 4) << 3);
    const int laB_h = (lane >> 3) & 1;

    // ---- load Q hi/lo (thread = query row) ----
    {
        size_t base = (size_t)(b * SEQ + w * WIN + tid) * (3 * DIM) + h * HD;
        const uint4* qhp = (const uint4*)(qh + base);
        const uint4* qlp = (const uint4*)(ql + base);
        #pragma unroll
        for (int c = 0; c < 8; c++) {
            uint32_t off = swz((uint32_t)tid, (uint32_t)c);
            *(uint4*)(smc + off)         = qhp[c];
            *(uint4*)(smc + 16384 + off) = qlp[c];
        }
    }

    float O[2][8][4];
    #pragma unroll
    for (int mt = 0; mt < 2; mt++)
        #pragma unroll
        for (int n8 = 0; n8 < 8; n8++)
            #pragma unroll
            for (int e = 0; e < 4; e++) O[mt][n8][e] = 0.f;
    float mS[2][2] = {{-1e30f, -1e30f}, {-1e30f, -1e30f}};
    float lS[2][2] = {{0.f, 0.f}, {0.f, 0.f}};

    for (int dw = -1; dw <= 1; dw++) {
        int wi = w + dw;
        if (wi < 0 || wi >= NW) continue;
        __syncthreads();
        // ---- load K,V hi/lo window (thread = key row) ----
        {
            size_t base = (size_t)(b * SEQ + wi * WIN + tid) * (3 * DIM) + h * HD;
            const uint4* khp = (const uint4*)(qh + base + DIM);
            const uint4* klp = (const uint4*)(ql + base + DIM);
            const uint4* vhp = (const uint4*)(qh + base + 2 * DIM);
            const uint4* vlp = (const uint4*)(ql + base + 2 * DIM);
            #pragma unroll
            for (int c = 0; c < 8; c++) {
                uint32_t off = swz((uint32_t)tid, (uint32_t)c);
                *(uint4*)(smc + 32768 + off) = khp[c];
                *(uint4*)(smc + 49152 + off) = klp[c];
                *(uint4*)(smc + 65536 + off) = vhp[c];
                *(uint4*)(smc + 81920 + off) = vlp[c];
            }
        }
        __syncthreads();

        #pragma unroll
        for (int c0 = 0; c0 < 128; c0 += 64) {
            float S[2][8][4];
            #pragma unroll
            for (int mt = 0; mt < 2; mt++)
                #pragma unroll
                for (int n8 = 0; n8 < 8; n8++)
                    #pragma unroll
                    for (int e = 0; e < 4; e++) S[mt][n8][e] = 0.f;

            #pragma unroll
            for (int kb = 0; kb < 4; kb++) {
                uint32_t aqh[2][4], aql[2][4], bkh[4][4], bkl[4][4];
                #pragma unroll
                for (int mt = 0; mt < 2; mt++) {
                    uint32_t row = warpM + mt * 16 + laA_r;
                    ldsm4(aqh[mt], sQh + swz(row, kb * 2 + laA_h));
                    ldsm4(aql[mt], sQl + swz(row, kb * 2 + laA_h));
                }
                #pragma unroll
                for (int np = 0; np < 4; np++) {
                    uint32_t row = c0 + np * 16 + laB_r;
                    ldsm4(bkh[np], sKh + swz(row, kb * 2 + laB_h));
                    ldsm4(bkl[np], sKl + swz(row, kb * 2 + laB_h));
                }
                #pragma unroll
                for (int mt = 0; mt < 2; mt++)
                    #pragma unroll
                    for (int n8 = 0; n8 < 8; n8++) {
                        const uint32_t* bh2 = &bkh[n8 >> 1][(n8 & 1) * 2];
                        const uint32_t* bl2 = &bkl[n8 >> 1][(n8 & 1) * 2];
                        mma16816(S[mt][n8], aqh[mt], bh2);
                        mma16816(S[mt][n8], aqh[mt], bl2);
                        mma16816(S[mt][n8], aql[mt], bh2);
                    }
            }

            #pragma unroll
            for (int mt = 0; mt < 2; mt++) {
                #pragma unroll
                for (int half = 0; half < 2; half++) {
                    float cm = -1e30f;
                    #pragma unroll
                    for (int n8 = 0; n8 < 8; n8++) {
                        cm = fmaxf(cm, S[mt][n8][half * 2 + 0]);
                        cm = fmaxf(cm, S[mt][n8][half * 2 + 1]);
                    }
                    cm = fmaxf(cm, __shfl_xor_sync(0xffffffffu, cm, 1));
                    cm = fmaxf(cm, __shfl_xor_sync(0xffffffffu, cm, 2));
                    float mn = fmaxf(mS[mt][half], cm);
                    float corr = __expf(mS[mt][half] - mn);
                    float rs = 0.f;
                    #pragma unroll
                    for (int n8 = 0; n8 < 8; n8++) {
                        float p0 = __expf(S[mt][n8][half * 2 + 0] - mn);
                        float p1 = __expf(S[mt][n8][half * 2 + 1] - mn);
                        S[mt][n8][half * 2 + 0] = p0;
                        S[mt][n8][half * 2 + 1] = p1;
                        rs += p0 + p1;
                    }
                    rs += __shfl_xor_sync(0xffffffffu, rs, 1);
                    rs += __shfl_xor_sync(0xffffffffu, rs, 2);
                    lS[mt][half] = lS[mt][half] * corr + rs;
                    mS[mt][half] = mn;
                    #pragma unroll
                    for (int n8 = 0; n8 < 8; n8++) {
                        O[mt][n8][half * 2 + 0] *= corr;
                        O[mt][n8][half * 2 + 1] *= corr;
                    }
                }
            }

            #pragma unroll
            for (int kb = 0; kb < 4; kb++) {
                uint32_t ph[2][4], pl[2][4];
                #pragma unroll
                for (int mt = 0; mt < 2; mt++) {
                    #pragma unroll
                    for (int i = 0; i < 4; i++) {
                        int j = 2 * kb + (i >> 1);
                        float p0 = S[mt][j][(i & 1) * 2 + 0];
                        float p1 = S[mt][j][(i & 1) * 2 + 1];
                        __nv_bfloat16 h0 = __float2bfloat16(p0);
                        __nv_bfloat16 h1 = __float2bfloat16(p1);
                        ph[mt][i] = pack_bf2(h0, h1);
                        pl[mt][i] = pack_bf2(
                            __float2bfloat16(p0 - __bfloat162float(h0)),
                            __float2bfloat16(p1 - __bfloat162float(h1)));
                    }
                }
                uint32_t vfh[4][4], vfl[4][4];
                #pragma unroll
                for (int np = 0; np < 4; np++) {
                    uint32_t row = c0 + kb * 16 + (lane & 15);
                    uint32_t ch = np * 2 + (lane >> 4);
                    ldsm4t(vfh[np], sVh + swz(row, ch));
                    ldsm4t(vfl[np], sVl + swz(row, ch));
                }
                #pragma unroll
                for (int mt = 0; mt < 2; mt++)
                    #pragma unroll
                    for (int n8 = 0; n8 < 8; n8++) {
                        const uint32_t* vh2 = &vfh[n8 >> 1][(n8 & 1) * 2];
                        const uint32_t* vl2 = &vfl[n8 >> 1][(n8 & 1) * 2];
                        mma16816(O[mt][n8], ph[mt], vh2);
                        mma16816(O[mt][n8], ph[mt], vl2);
                        mma16816(O[mt][n8], pl[mt], vh2);
                    }
            }
        }
    }

    #pragma unroll
    for (int mt = 0; mt < 2; mt++) {
        #pragma unroll
        for (int half = 0; half < 2; half++) {
            float inv = 1.f / lS[mt][half];
            int row = warpM + mt * 16 + (lane >> 2) + half * 8;
            size_t base = (size_t)(b * SEQ + w * WIN + row) * DIM + h * HD;
            #pragma unroll
            for (int n8 = 0; n8 < 8; n8++) {
                int col = n8 * 8 + (lane & 3) * 2;
                float x0 = O[mt][n8][half * 2 + 0] * inv;
                float x1 = O[mt][n8][half * 2 + 1] * inv;
                __nv_bfloat16 h0, l0, h1, l1;
                split_hl(x0, h0, l0); split_hl(x1, h1, l1);
                *(uint32_t*)(oh + base + col) = pack_bf2(h0, h1);
                *(uint32_t*)(ol + base + col) = pack_bf2(l0, l1);
            }
        }
    }
}

// ---------------- host orchestration ---------------------------------------
extern "C" void kernel_launch(void* const* d_in, const int* in_sizes, int n_in,
                              void* d_out, int out_size) {
    const float* x      = (const float*)d_in[0];
    const float* t_emb  = (const float*)d_in[1];
    const float* ln1_g  = (const float*)d_in[2];
    const float* ln1_b  = (const float*)d_in[3];
    const float* qkv_w  = (const float*)d_in[4];
    const float* qkv_b  = (const float*)d_in[5];
    const float* proj_w = (const float*)d_in[6];
    const float* proj_b = (const float*)d_in[7];
    const float* ln2_g  = (const float*)d_in[8];
    const float* ln2_b  = (const float*)d_in[9];
    const float* mlp_w1 = (const float*)d_in[10];
    const float* mlp_b1 = (const float*)d_in[11];
    const float* mlp_w2 = (const float*)d_in[12];
    const float* mlp_b2 = (const float*)d_in[13];
    const float* time_w = (const float*)d_in[14];
    const float* time_b = (const float*)d_in[15];
    float* out = (float*)d_out;

    void* p;
    float* y;
    __nv_bfloat16 *xh, *xl, *ah, *al, *fh, *fl, *qh, *ql;
    __nv_bfloat16 *wq_h, *wq_l, *wp_h, *wp_l, *w1_h, *w1_l, *w2_h, *w2_l;
    cudaGetSymbolAddress(&p, g_y);    y   = (float*)p;
    cudaGetSymbolAddress(&p, g_xh);   xh  = (__nv_bfloat16*)p;
    cudaGetSymbolAddress(&p, g_xl);   xl  = (__nv_bfloat16*)p;
    cudaGetSymbolAddress(&p, g_ah);   ah  = (__nv_bfloat16*)p;
    cudaGetSymbolAddress(&p, g_al);   al  = (__nv_bfloat16*)p;
    cudaGetSymbolAddress(&p, g_fh);   fh  = (__nv_bfloat16*)p;
    cudaGetSymbolAddress(&p, g_fl);   fl  = (__nv_bfloat16*)p;
    cudaGetSymbolAddress(&p, g_qh);   qh  = (__nv_bfloat16*)p;
    cudaGetSymbolAddress(&p, g_ql);   ql  = (__nv_bfloat16*)p;
    cudaGetSymbolAddress(&p, g_wq_h); wq_h = (__nv_bfloat16*)p;
    cudaGetSymbolAddress(&p, g_wq_l); wq_l = (__nv_bfloat16*)p;
    cudaGetSymbolAddress(&p, g_wp_h); wp_h = (__nv_bfloat16*)p;
    cudaGetSymbolAddress(&p, g_wp_l); wp_l = (__nv_bfloat16*)p;
    cudaGetSymbolAddress(&p, g_w1_h); w1_h = (__nv_bfloat16*)p;
    cudaGetSymbolAddress(&p, g_w1_l); w1_l = (__nv_bfloat16*)p;
    cudaGetSymbolAddress(&p, g_w2_h); w2_h = (__nv_bfloat16*)p;
    cudaGetSymbolAddress(&p, g_w2_l); w2_l = (__nv_bfloat16*)p;

    const int gemm_smem = 3 * STG;   // 96 KB (3-stage)
    cudaFuncSetAttribute(mma_gemm<0>, cudaFuncAttributeMaxDynamicSharedMemorySize, gemm_smem);
    cudaFuncSetAttribute(mma_gemm<1>, cudaFuncAttributeMaxDynamicSharedMemorySize, gemm_smem);
    cudaFuncSetAttribute(mma_gemm<2>, cudaFuncAttributeMaxDynamicSharedMemorySize, gemm_smem);
    cudaFuncSetAttribute(mma_gemm<3>, cudaFuncAttributeMaxDynamicSharedMemorySize, gemm_smem);
    const int attn_smem = 98304;    // Q/K/V hi+lo, 16KB each
    cudaFuncSetAttribute(attn_mma_kernel, cudaFuncAttributeMaxDynamicSharedMemorySize, attn_smem);

    // 0. weight prep
    wprep_kernel<<<dim3(1536 / 32, 512 / 32), dim3(32, 8)>>>(qkv_w,  wq_h, wq_l, 512, 1536);
    wprep_kernel<<<dim3(512 / 32,  512 / 32), dim3(32, 8)>>>(proj_w, wp_h, wp_l, 512, 512);
    wprep_kernel<<<dim3(2048 / 32, 512 / 32), dim3(32, 8)>>>(mlp_w1, w1_h, w1_l, 512, 2048);
    wprep_kernel<<<dim3(512 / 32, 2048 / 32), dim3(32, 8)>>>(mlp_w2, w2_h, w2_l, 2048, 512);
    // 1. adaLN scale/shift
    time_mlp_kernel<<<dim3(2 * DIM / 256, B_), 256>>>(t_emb, time_w, time_b);
    // 2. modulated LN1 -> bf16 hi/lo
    ln_kernel<1><<<NTOK, 128>>>(x, ln1_g, ln1_b, xh, xl);
    // 3. QKV GEMM -> bf16 hi/lo (Q pre-scaled)
    mma_gemm<3><<<dim3(12, NTOK / 128), 256, gemm_smem>>>(
        xh, xl, wq_h, wq_l, qkv_b, nullptr, nullptr, qh, ql, 512, 1536);
    // 4. local attention (tensor cores) -> bf16 hi/lo
    attn_mma_kernel<<<dim3(NW, HEADS, B_), 128, attn_smem>>>(qh, ql, ah, al);
    // 5. proj + residual(x) -> fp32 y
    mma_gemm<1><<<dim3(4, NTOK / 128), 256, gemm_smem>>>(
        ah, al, wp_h, wp_l, proj_b, x, y, nullptr, nullptr, 512, 512);
    // 6. LN2 -> bf16 hi/lo
    ln_kernel<0><<<NTOK, 128>>>(y, ln2_g, ln2_b, xh, xl);
    // 7. MLP up + GELU -> bf16 hi/lo
    mma_gemm<2><<<dim3(16, NTOK / 128), 256, gemm_smem>>>(
        xh, xl, w1_h, w1_l, mlp_b1, nullptr, nullptr, fh, fl, 512, 2048);
    // 8. MLP down + residual(y) -> out
    mma_gemm<1><<<dim3(4, NTOK / 128), 256, gemm_smem>>>(
        fh, fl, w2_h, w2_l, mlp_b2, y, out, nullptr, nullptr, 2048, 512);
}

// round 7
// speedup vs baseline: 1.1111x; 1.1111x over previous
#include <cuda_runtime.h>
#include <cuda_bf16.h>
#include <math.h>
#include <cstdint>

#define B_    8
#define SEQ   8192
#define DIM   512
#define HEADS 8
#define HD    64
#define FF_   2048
#define WIN   128
#define TD    512
#define NTOK  (B_*SEQ)        // 65536
#define NW    (SEQ/WIN)       // 64

// ---------------- scratch (device globals; no runtime allocation) ----------
__device__ float g_ss  [B_ * 2 * DIM];
__device__ float g_qkv [(size_t)NTOK * 3 * DIM];   // fp32 qkv
__device__ float g_y   [(size_t)NTOK * DIM];       // x + proj(attn), fp32
// hi/lo bf16 activations (GEMM A operands)
__device__ __nv_bfloat16 g_xh [(size_t)NTOK * DIM],  g_xl [(size_t)NTOK * DIM];
__device__ __nv_bfloat16 g_ah [(size_t)NTOK * DIM],  g_al [(size_t)NTOK * DIM];
__device__ __nv_bfloat16 g_fh [(size_t)NTOK * FF_],  g_fl [(size_t)NTOK * FF_];
// weights hi/lo, transposed to [N][K] bf16 (K contiguous)
__device__ __nv_bfloat16 g_wq_h[1536 * 512],  g_wq_l[1536 * 512];
__device__ __nv_bfloat16 g_wp_h[512 * 512],   g_wp_l[512 * 512];
__device__ __nv_bfloat16 g_w1_h[2048 * 512],  g_w1_l[2048 * 512];
__device__ __nv_bfloat16 g_w2_h[512 * 2048],  g_w2_l[512 * 2048];

// ---------------- PTX helpers ----------------------------------------------
__device__ __forceinline__ uint32_t smem_u32(const void* p) {
    uint32_t a;
    asm("{ .reg .u64 t; cvta.to.shared.u64 t, %1; cvt.u32.u64 %0, t; }"
        : "=r"(a) : "l"(p));
    return a;
}
__device__ __forceinline__ void cp16(uint32_t dst, const void* src) {
    asm volatile("cp.async.cg.shared.global [%0], [%1], 16;"
                 :: "r"(dst), "l"(src) : "memory");
}
#define CP_COMMIT() asm volatile("cp.async.commit_group;" ::: "memory")
#define CP_WAIT(n)  asm volatile("cp.async.wait_group %0;" :: "n"(n) : "memory")

__device__ __forceinline__ void ldsm4(uint32_t* r, uint32_t addr) {
    asm volatile("ldmatrix.sync.aligned.m8n8.x4.shared.b16 {%0,%1,%2,%3}, [%4];"
                 : "=r"(r[0]), "=r"(r[1]), "=r"(r[2]), "=r"(r[3]) : "r"(addr));
}
__device__ __forceinline__ void ldsm4t(uint32_t* r, uint32_t addr) {
    asm volatile("ldmatrix.sync.aligned.m8n8.x4.trans.shared.b16 {%0,%1,%2,%3}, [%4];"
                 : "=r"(r[0]), "=r"(r[1]), "=r"(r[2]), "=r"(r[3]) : "r"(addr));
}
__device__ __forceinline__ void mma16816(float* d, const uint32_t* a,
                                         const uint32_t* b) {
    asm volatile(
        "mma.sync.aligned.m16n8k16.row.col.f32.bf16.bf16.f32 "
        "{%0,%1,%2,%3}, {%4,%5,%6,%7}, {%8,%9}, {%0,%1,%2,%3};"
        : "+f"(d[0]), "+f"(d[1]), "+f"(d[2]), "+f"(d[3])
        : "r"(a[0]), "r"(a[1]), "r"(a[2]), "r"(a[3]), "r"(b[0]), "r"(b[1]));
}
__device__ __forceinline__ uint32_t swz(uint32_t r, uint32_t c16) {
    return (r << 7) + ((c16 ^ (r & 7)) << 4);
}
__device__ __forceinline__ void split_hl(float v, __nv_bfloat16& h, __nv_bfloat16& l) {
    h = __float2bfloat16(v);
    l = __float2bfloat16(v - __bfloat162float(h));
}
__device__ __forceinline__ uint32_t pack_bf2(__nv_bfloat16 a, __nv_bfloat16 b) {
    __nv_bfloat162 p = __halves2bfloat162(a, b);
    return *reinterpret_cast<uint32_t*>(&p);
}

// ---------------- kernel 0: coalesced weight transpose + hi/lo split -------
__global__ void wprep_kernel(const float* __restrict__ W,
                             __nv_bfloat16* __restrict__ oh,
                             __nv_bfloat16* __restrict__ ol, int K, int N) {
    __shared__ float tile[32][33];
    int bx = blockIdx.x * 32, by = blockIdx.y * 32;
    int tx = threadIdx.x, ty = threadIdx.y;
    #pragma unroll
    for (int i = 0; i < 4; i++) {
        int k = by + ty + i * 8;
        tile[ty + i * 8][tx] = W[(size_t)k * N + bx + tx];
    }
    __syncthreads();
    #pragma unroll
    for (int i = 0; i < 4; i++) {
        int n = bx + ty + i * 8;
        int k = by + tx;
        float v = tile[tx][ty + i * 8];
        __nv_bfloat16 h, l; split_hl(v, h, l);
        oh[(size_t)n * K + k] = h;
        ol[(size_t)n * K + k] = l;
    }
}

// ---------------- kernel 1: ss = silu(t_emb) @ time_w + time_b -------------
__global__ void time_mlp_kernel(const float* __restrict__ te,
                                const float* __restrict__ tw,
                                const float* __restrict__ tb) {
    __shared__ float st[TD];
    int b = blockIdx.y;
    for (int k = threadIdx.x; k < TD; k += blockDim.x) {
        float v = te[b * TD + k];
        st[k] = v / (1.f + __expf(-v));
    }
    __syncthreads();
    int j = blockIdx.x * blockDim.x + threadIdx.x;
    float acc = tb[j];
    for (int k = 0; k < TD; k++)
        acc = fmaf(st[k], tw[k * (2 * DIM) + j], acc);
    g_ss[b * 2 * DIM + j] = acc;
}

// ---------------- kernel 2: LayerNorm -> bf16 hi/lo ------------------------
template <int MOD>
__global__ void ln_kernel(const float* __restrict__ x,
                          const float* __restrict__ gam,
                          const float* __restrict__ bet,
                          __nv_bfloat16* __restrict__ oh,
                          __nv_bfloat16* __restrict__ ol) {
    int row  = blockIdx.x;
    int t    = threadIdx.x;
    int lane = t & 31, wid = t >> 5;
    float4 xv = ((const float4*)(x + (size_t)row * DIM))[t];
    float s  = xv.x + xv.y + xv.z + xv.w;
    float s2 = fmaf(xv.x, xv.x, fmaf(xv.y, xv.y, fmaf(xv.z, xv.z, xv.w * xv.w)));
    #pragma unroll
    for (int o = 16; o > 0; o >>= 1) {
        s  += __shfl_xor_sync(0xffffffffu, s,  o);
        s2 += __shfl_xor_sync(0xffffffffu, s2, o);
    }
    __shared__ float red[8];
    if (lane == 0) { red[wid] = s; red[4 + wid] = s2; }
    __syncthreads();
    s  = red[0] + red[1] + red[2] + red[3];
    s2 = red[4] + red[5] + red[6] + red[7];
    float mu   = s * (1.f / DIM);
    float var  = s2 * (1.f / DIM) - mu * mu;
    float rstd = rsqrtf(var + 1e-5f);

    float4 gg = ((const float4*)gam)[t];
    float4 bb = ((const float4*)bet)[t];
    float o4[4];
    o4[0] = (xv.x - mu) * rstd * gg.x + bb.x;
    o4[1] = (xv.y - mu) * rstd * gg.y + bb.y;
    o4[2] = (xv.z - mu) * rstd * gg.z + bb.z;
    o4[3] = (xv.w - mu) * rstd * gg.w + bb.w;
    if (MOD) {
        int b = row >> 13;
        float4 sc = ((const float4*)(g_ss + b * 2 * DIM))[t];
        float4 sh = ((const float4*)(g_ss + b * 2 * DIM + DIM))[t];
        o4[0] = o4[0] * (1.f + sc.x) + sh.x;
        o4[1] = o4[1] * (1.f + sc.y) + sh.y;
        o4[2] = o4[2] * (1.f + sc.z) + sh.z;
        o4[3] = o4[3] * (1.f + sc.w) + sh.w;
    }
    __nv_bfloat16 h[4], l[4];
    #pragma unroll
    for (int i = 0; i < 4; i++) split_hl(o4[i], h[i], l[i]);
    ((uint2*)(oh + (size_t)row * DIM))[t] =
        make_uint2(pack_bf2(h[0], h[1]), pack_bf2(h[2], h[3]));
    ((uint2*)(ol + (size_t)row * DIM))[t] =
        make_uint2(pack_bf2(l[0], l[1]), pack_bf2(l[2], l[3]));
}

// ---------------- kernel 3: mma.sync bf16 GEMM, 2-stage pipeline -----------
// Mainloop regrouped by k16 index: each fragment loaded exactly once
// (24 ldsm.x4 / K-iter instead of 36).
// EPI: 0 = bias -> f32; 1 = bias+res -> f32; 2 = bias+GELU -> hi/lo
#define KSTEP 32
template <int EPI>
__global__ __launch_bounds__(256, 2)
void mma_gemm(const __nv_bfloat16* __restrict__ Ah,
              const __nv_bfloat16* __restrict__ Al,
              const __nv_bfloat16* __restrict__ Bh,
              const __nv_bfloat16* __restrict__ Bl,
              const float* __restrict__ bias,
              const float* __restrict__ res,
              float* __restrict__ Cf,
              __nv_bfloat16* __restrict__ Ch,
              __nv_bfloat16* __restrict__ Cl,
              int K, int N) {
    extern __shared__ char smem[];
    const uint32_t sbase = smem_u32(smem);
    const int tid = threadIdx.x, w = tid >> 5, lane = tid & 31;
    const int bm = blockIdx.y * 128, bn = blockIdx.x * 128;
    const int warpM = (w >> 2) * 64, warpN = (w & 3) * 32;
    const int T = K / KSTEP;

    const int r_ld = tid >> 3, c_ld = tid & 7;

    auto issue = [&](int t) {
        int k0 = t * KSTEP;
        uint32_t sa = sbase + (t & 1) * 32768;
        uint32_t sb = sa + 16384;
        #pragma unroll
        for (int i = 0; i < 4; i++) {
            int r = r_ld + i * 32;
            const __nv_bfloat16* srcA = (c_ld < 4)
                ? Ah + (size_t)(bm + r) * K + k0 + c_ld * 8
                : Al + (size_t)(bm + r) * K + k0 + (c_ld - 4) * 8;
            cp16(sa + swz(r, c_ld), srcA);
            const __nv_bfloat16* srcB = (c_ld < 4)
                ? Bh + (size_t)(bn + r) * K + k0 + c_ld * 8
                : Bl + (size_t)(bn + r) * K + k0 + (c_ld - 4) * 8;
            cp16(sb + swz(r, c_ld), srcB);
        }
        CP_COMMIT();
    };

    float acc[4][4][4];
    #pragma unroll
    for (int i = 0; i < 4; i++)
        #pragma unroll
        for (int j = 0; j < 4; j++)
            #pragma unroll
            for (int e = 0; e < 4; e++) acc[i][j][e] = 0.f;

    const int laA_r = lane & 15, laA_h = lane >> 4;
    const int laB_r = (lane & 7) + ((lane >> 4) << 3);
    const int laB_h = (lane >> 3) & 1;

    issue(0);
    for (int t = 0; t < T; t++) {
        if (t + 1 < T) { issue(t + 1); CP_WAIT(1); }
        else           { CP_WAIT(0); }
        __syncthreads();

        uint32_t sa = sbase + (t & 1) * 32768;
        uint32_t sb = sa + 16384;
        // group by k16 index i: load Ah(i), Al(i), Bh(i), Bl(i) ONCE,
        // fire the three split terms AhBh + AhBl + AlBh.
        #pragma unroll
        for (int i = 0; i < 2; i++) {
            uint32_t afh[4][4], afl[4][4], bfh[2][4], bfl[2][4];
            #pragma unroll
            for (int mi = 0; mi < 4; mi++) {
                uint32_t row = warpM + mi * 16 + laA_r;
                ldsm4(afh[mi], sa + swz(row, 2 * i + laA_h));
                ldsm4(afl[mi], sa + swz(row, 4 + 2 * i + laA_h));
            }
            #pragma unroll
            for (int nj = 0; nj < 2; nj++) {
                uint32_t row = warpN + nj * 16 + laB_r;
                ldsm4(bfh[nj], sb + swz(row, 2 * i + laB_h));
                ldsm4(bfl[nj], sb + swz(row, 4 + 2 * i + laB_h));
            }
            #pragma unroll
            for (int mi = 0; mi < 4; mi++)
                #pragma unroll
                for (int n8 = 0; n8 < 4; n8++) {
                    const uint32_t* bh2 = &bfh[n8 >> 1][(n8 & 1) * 2];
                    const uint32_t* bl2 = &bfl[n8 >> 1][(n8 & 1) * 2];
                    mma16816(acc[mi][n8], afh[mi], bh2);
                    mma16816(acc[mi][n8], afh[mi], bl2);
                    mma16816(acc[mi][n8], afl[mi], bh2);
                }
        }
        __syncthreads();
    }

    int tr = lane >> 2, tc = (lane & 3) * 2;
    #pragma unroll
    for (int mi = 0; mi < 4; mi++) {
        #pragma unroll
        for (int half = 0; half < 2; half++) {
            int row = bm + warpM + mi * 16 + tr + half * 8;
            size_t rowoff = (size_t)row * N;
            #pragma unroll
            for (int n8 = 0; n8 < 4; n8++) {
                int col = bn + warpN + n8 * 8 + tc;
                float2 bi = *(const float2*)(bias + col);
                float ox = acc[mi][n8][half * 2 + 0] + bi.x;
                float oy = acc[mi][n8][half * 2 + 1] + bi.y;
                if (EPI == 1) {
                    float2 rr = *(const float2*)(res + rowoff + col);
                    ox += rr.x; oy += rr.y;
                }
                if (EPI == 2) {
                    ox = 0.5f * ox * (1.f + erff(ox * 0.70710678118654752f));
                    oy = 0.5f * oy * (1.f + erff(oy * 0.70710678118654752f));
                    __nv_bfloat16 hx, lx, hy, ly;
                    split_hl(ox, hx, lx); split_hl(oy, hy, ly);
                    *(uint32_t*)(Ch + rowoff + col) = pack_bf2(hx, hy);
                    *(uint32_t*)(Cl + rowoff + col) = pack_bf2(lx, ly);
                } else {
                    *(float2*)(Cf + rowoff + col) = make_float2(ox, oy);
                }
            }
        }
    }
}

// ---------------- kernel 4: local windowed attention via mma.sync ----------
__global__ __launch_bounds__(128)
void attn_mma_kernel(const float* __restrict__ qkv,
                     __nv_bfloat16* __restrict__ oh,
                     __nv_bfloat16* __restrict__ ol) {
    extern __shared__ char smc[];
    const uint32_t sQh = smem_u32(smc);
    const uint32_t sQl = sQh + 16384;
    const uint32_t sKh = sQh + 32768;
    const uint32_t sKl = sQh + 49152;
    const uint32_t sVh = sQh + 65536;
    const uint32_t sVl = sQh + 81920;

    const int w = blockIdx.x, h = blockIdx.y, b = blockIdx.z;
    const int tid = threadIdx.x, lane = tid & 31;
    const int warpM = (tid >> 5) * 32;

    const int laA_r = lane & 15, laA_h = lane >> 4;
    const int laB_r = (lane & 7) + ((lane >> 4) << 3);
    const int laB_h = (lane >> 3) & 1;

    // ---- load Q (x 0.125) -> hi/lo smem (thread = query row) ----
    {
        const float* qp = qkv + (size_t)(b * SEQ + w * WIN + tid) * (3 * DIM) + h * HD;
        #pragma unroll
        for (int c = 0; c < 8; c++) {
            float4 v0 = ((const float4*)qp)[c * 2];
            float4 v1 = ((const float4*)qp)[c * 2 + 1];
            float f[8] = {v0.x, v0.y, v0.z, v0.w, v1.x, v1.y, v1.z, v1.w};
            uint32_t hp[4], lp[4];
            #pragma unroll
            for (int e = 0; e < 4; e++) {
                __nv_bfloat16 h0, l0, h1, l1;
                split_hl(f[2 * e] * 0.125f, h0, l0);
                split_hl(f[2 * e + 1] * 0.125f, h1, l1);
                hp[e] = pack_bf2(h0, h1);
                lp[e] = pack_bf2(l0, l1);
            }
            uint32_t off = swz((uint32_t)tid, (uint32_t)c);
            *(uint4*)(smc + off)         = make_uint4(hp[0], hp[1], hp[2], hp[3]);
            *(uint4*)(smc + 16384 + off) = make_uint4(lp[0], lp[1], lp[2], lp[3]);
        }
    }

    float O[2][8][4];
    #pragma unroll
    for (int mt = 0; mt < 2; mt++)
        #pragma unroll
        for (int n8 = 0; n8 < 8; n8++)
            #pragma unroll
            for (int e = 0; e < 4; e++) O[mt][n8][e] = 0.f;
    float mS[2][2] = {{-1e30f, -1e30f}, {-1e30f, -1e30f}};
    float lS[2][2] = {{0.f, 0.f}, {0.f, 0.f}};

    for (int dw = -1; dw <= 1; dw++) {
        int wi = w + dw;
        if (wi < 0 || wi >= NW) continue;
        __syncthreads();
        // ---- load K,V window -> hi/lo smem (thread = key row) ----
        {
            const float* kp = qkv + (size_t)(b * SEQ + wi * WIN + tid) * (3 * DIM) + DIM + h * HD;
            const float* vp = kp + DIM;
            #pragma unroll
            for (int c = 0; c < 8; c++) {
                float4 k0 = ((const float4*)kp)[c * 2];
                float4 k1 = ((const float4*)kp)[c * 2 + 1];
                float4 u0 = ((const float4*)vp)[c * 2];
                float4 u1 = ((const float4*)vp)[c * 2 + 1];
                float fk[8] = {k0.x, k0.y, k0.z, k0.w, k1.x, k1.y, k1.z, k1.w};
                float fv[8] = {u0.x, u0.y, u0.z, u0.w, u1.x, u1.y, u1.z, u1.w};
                uint32_t kh[4], kl[4], vh[4], vl[4];
                #pragma unroll
                for (int e = 0; e < 4; e++) {
                    __nv_bfloat16 a0, b0, a1, b1;
                    split_hl(fk[2 * e], a0, b0); split_hl(fk[2 * e + 1], a1, b1);
                    kh[e] = pack_bf2(a0, a1); kl[e] = pack_bf2(b0, b1);
                    split_hl(fv[2 * e], a0, b0); split_hl(fv[2 * e + 1], a1, b1);
                    vh[e] = pack_bf2(a0, a1); vl[e] = pack_bf2(b0, b1);
                }
                uint32_t off = swz((uint32_t)tid, (uint32_t)c);
                *(uint4*)(smc + 32768 + off) = make_uint4(kh[0], kh[1], kh[2], kh[3]);
                *(uint4*)(smc + 49152 + off) = make_uint4(kl[0], kl[1], kl[2], kl[3]);
                *(uint4*)(smc + 65536 + off) = make_uint4(vh[0], vh[1], vh[2], vh[3]);
                *(uint4*)(smc + 81920 + off) = make_uint4(vl[0], vl[1], vl[2], vl[3]);
            }
        }
        __syncthreads();

        #pragma unroll
        for (int c0 = 0; c0 < 128; c0 += 64) {
            float S[2][8][4];
            #pragma unroll
            for (int mt = 0; mt < 2; mt++)
                #pragma unroll
                for (int n8 = 0; n8 < 8; n8++)
                    #pragma unroll
                    for (int e = 0; e < 4; e++) S[mt][n8][e] = 0.f;

            #pragma unroll
            for (int kb = 0; kb < 4; kb++) {
                uint32_t aqh[2][4], aql[2][4], bkh[4][4], bkl[4][4];
                #pragma unroll
                for (int mt = 0; mt < 2; mt++) {
                    uint32_t row = warpM + mt * 16 + laA_r;
                    ldsm4(aqh[mt], sQh + swz(row, kb * 2 + laA_h));
                    ldsm4(aql[mt], sQl + swz(row, kb * 2 + laA_h));
                }
                #pragma unroll
                for (int np = 0; np < 4; np++) {
                    uint32_t row = c0 + np * 16 + laB_r;
                    ldsm4(bkh[np], sKh + swz(row, kb * 2 + laB_h));
                    ldsm4(bkl[np], sKl + swz(row, kb * 2 + laB_h));
                }
                #pragma unroll
                for (int mt = 0; mt < 2; mt++)
                    #pragma unroll
                    for (int n8 = 0; n8 < 8; n8++) {
                        const uint32_t* bh2 = &bkh[n8 >> 1][(n8 & 1) * 2];
                        const uint32_t* bl2 = &bkl[n8 >> 1][(n8 & 1) * 2];
                        mma16816(S[mt][n8], aqh[mt], bh2);
                        mma16816(S[mt][n8], aqh[mt], bl2);
                        mma16816(S[mt][n8], aql[mt], bh2);
                    }
            }

            #pragma unroll
            for (int mt = 0; mt < 2; mt++) {
                #pragma unroll
                for (int half = 0; half < 2; half++) {
                    float cm = -1e30f;
                    #pragma unroll
                    for (int n8 = 0; n8 < 8; n8++) {
                        cm = fmaxf(cm, S[mt][n8][half * 2 + 0]);
                        cm = fmaxf(cm, S[mt][n8][half * 2 + 1]);
                    }
                    cm = fmaxf(cm, __shfl_xor_sync(0xffffffffu, cm, 1));
                    cm = fmaxf(cm, __shfl_xor_sync(0xffffffffu, cm, 2));
                    float mn = fmaxf(mS[mt][half], cm);
                    float corr = __expf(mS[mt][half] - mn);
                    float rs = 0.f;
                    #pragma unroll
                    for (int n8 = 0; n8 < 8; n8++) {
                        float p0 = __expf(S[mt][n8][half * 2 + 0] - mn);
                        float p1 = __expf(S[mt][n8][half * 2 + 1] - mn);
                        S[mt][n8][half * 2 + 0] = p0;
                        S[mt][n8][half * 2 + 1] = p1;
                        rs += p0 + p1;
                    }
                    rs += __shfl_xor_sync(0xffffffffu, rs, 1);
                    rs += __shfl_xor_sync(0xffffffffu, rs, 2);
                    lS[mt][half] = lS[mt][half] * corr + rs;
                    mS[mt][half] = mn;
                    #pragma unroll
                    for (int n8 = 0; n8 < 8; n8++) {
                        O[mt][n8][half * 2 + 0] *= corr;
                        O[mt][n8][half * 2 + 1] *= corr;
                    }
                }
            }

            #pragma unroll
            for (int kb = 0; kb < 4; kb++) {
                uint32_t ph[2][4], pl[2][4];
                #pragma unroll
                for (int mt = 0; mt < 2; mt++) {
                    #pragma unroll
                    for (int i = 0; i < 4; i++) {
                        int j = 2 * kb + (i >> 1);
                        float p0 = S[mt][j][(i & 1) * 2 + 0];
                        float p1 = S[mt][j][(i & 1) * 2 + 1];
                        __nv_bfloat16 h0 = __float2bfloat16(p0);
                        __nv_bfloat16 h1 = __float2bfloat16(p1);
                        ph[mt][i] = pack_bf2(h0, h1);
                        pl[mt][i] = pack_bf2(
                            __float2bfloat16(p0 - __bfloat162float(h0)),
                            __float2bfloat16(p1 - __bfloat162float(h1)));
                    }
                }
                uint32_t vfh[4][4], vfl[4][4];
                #pragma unroll
                for (int np = 0; np < 4; np++) {
                    uint32_t row = c0 + kb * 16 + (lane & 15);
                    uint32_t ch = np * 2 + (lane >> 4);
                    ldsm4t(vfh[np], sVh + swz(row, ch));
                    ldsm4t(vfl[np], sVl + swz(row, ch));
                }
                #pragma unroll
                for (int mt = 0; mt < 2; mt++)
                    #pragma unroll
                    for (int n8 = 0; n8 < 8; n8++) {
                        const uint32_t* vh2 = &vfh[n8 >> 1][(n8 & 1) * 2];
                        const uint32_t* vl2 = &vfl[n8 >> 1][(n8 & 1) * 2];
                        mma16816(O[mt][n8], ph[mt], vh2);
                        mma16816(O[mt][n8], ph[mt], vl2);
                        mma16816(O[mt][n8], pl[mt], vh2);
                    }
            }
        }
    }

    #pragma unroll
    for (int mt = 0; mt < 2; mt++) {
        #pragma unroll
        for (int half = 0; half < 2; half++) {
            float inv = 1.f / lS[mt][half];
            int row = warpM + mt * 16 + (lane >> 2) + half * 8;
            size_t base = (size_t)(b * SEQ + w * WIN + row) * DIM + h * HD;
            #pragma unroll
            for (int n8 = 0; n8 < 8; n8++) {
                int col = n8 * 8 + (lane & 3) * 2;
                float x0 = O[mt][n8][half * 2 + 0] * inv;
                float x1 = O[mt][n8][half * 2 + 1] * inv;
                __nv_bfloat16 h0, l0, h1, l1;
                split_hl(x0, h0, l0); split_hl(x1, h1, l1);
                *(uint32_t*)(oh + base + col) = pack_bf2(h0, h1);
                *(uint32_t*)(ol + base + col) = pack_bf2(l0, l1);
            }
        }
    }
}

// ---------------- host orchestration ---------------------------------------
extern "C" void kernel_launch(void* const* d_in, const int* in_sizes, int n_in,
                              void* d_out, int out_size) {
    const float* x      = (const float*)d_in[0];
    const float* t_emb  = (const float*)d_in[1];
    const float* ln1_g  = (const float*)d_in[2];
    const float* ln1_b  = (const float*)d_in[3];
    const float* qkv_w  = (const float*)d_in[4];
    const float* qkv_b  = (const float*)d_in[5];
    const float* proj_w = (const float*)d_in[6];
    const float* proj_b = (const float*)d_in[7];
    const float* ln2_g  = (const float*)d_in[8];
    const float* ln2_b  = (const float*)d_in[9];
    const float* mlp_w1 = (const float*)d_in[10];
    const float* mlp_b1 = (const float*)d_in[11];
    const float* mlp_w2 = (const float*)d_in[12];
    const float* mlp_b2 = (const float*)d_in[13];
    const float* time_w = (const float*)d_in[14];
    const float* time_b = (const float*)d_in[15];
    float* out = (float*)d_out;

    void* p;
    float *qkv, *y;
    __nv_bfloat16 *xh, *xl, *ah, *al, *fh, *fl;
    __nv_bfloat16 *wq_h, *wq_l, *wp_h, *wp_l, *w1_h, *w1_l, *w2_h, *w2_l;
    cudaGetSymbolAddress(&p, g_qkv);  qkv = (float*)p;
    cudaGetSymbolAddress(&p, g_y);    y   = (float*)p;
    cudaGetSymbolAddress(&p, g_xh);   xh  = (__nv_bfloat16*)p;
    cudaGetSymbolAddress(&p, g_xl);   xl  = (__nv_bfloat16*)p;
    cudaGetSymbolAddress(&p, g_ah);   ah  = (__nv_bfloat16*)p;
    cudaGetSymbolAddress(&p, g_al);   al  = (__nv_bfloat16*)p;
    cudaGetSymbolAddress(&p, g_fh);   fh  = (__nv_bfloat16*)p;
    cudaGetSymbolAddress(&p, g_fl);   fl  = (__nv_bfloat16*)p;
    cudaGetSymbolAddress(&p, g_wq_h); wq_h = (__nv_bfloat16*)p;
    cudaGetSymbolAddress(&p, g_wq_l); wq_l = (__nv_bfloat16*)p;
    cudaGetSymbolAddress(&p, g_wp_h); wp_h = (__nv_bfloat16*)p;
    cudaGetSymbolAddress(&p, g_wp_l); wp_l = (__nv_bfloat16*)p;
    cudaGetSymbolAddress(&p, g_w1_h); w1_h = (__nv_bfloat16*)p;
    cudaGetSymbolAddress(&p, g_w1_l); w1_l = (__nv_bfloat16*)p;
    cudaGetSymbolAddress(&p, g_w2_h); w2_h = (__nv_bfloat16*)p;
    cudaGetSymbolAddress(&p, g_w2_l); w2_l = (__nv_bfloat16*)p;

    const int gemm_smem = 65536;
    cudaFuncSetAttribute(mma_gemm<0>, cudaFuncAttributeMaxDynamicSharedMemorySize, gemm_smem);
    cudaFuncSetAttribute(mma_gemm<1>, cudaFuncAttributeMaxDynamicSharedMemorySize, gemm_smem);
    cudaFuncSetAttribute(mma_gemm<2>, cudaFuncAttributeMaxDynamicSharedMemorySize, gemm_smem);
    const int attn_smem = 98304;    // Q/K/V hi+lo, 16KB each
    cudaFuncSetAttribute(attn_mma_kernel, cudaFuncAttributeMaxDynamicSharedMemorySize, attn_smem);

    // 0. weight prep (coalesced transpose + hi/lo split)
    wprep_kernel<<<dim3(1536 / 32, 512 / 32), dim3(32, 8)>>>(qkv_w,  wq_h, wq_l, 512, 1536);
    wprep_kernel<<<dim3(512 / 32,  512 / 32), dim3(32, 8)>>>(proj_w, wp_h, wp_l, 512, 512);
    wprep_kernel<<<dim3(2048 / 32, 512 / 32), dim3(32, 8)>>>(mlp_w1, w1_h, w1_l, 512, 2048);
    wprep_kernel<<<dim3(512 / 32, 2048 / 32), dim3(32, 8)>>>(mlp_w2, w2_h, w2_l, 2048, 512);
    // 1. adaLN scale/shift
    time_mlp_kernel<<<dim3(2 * DIM / 256, B_), 256>>>(t_emb, time_w, time_b);
    // 2. modulated LN1 -> bf16 hi/lo
    ln_kernel<1><<<NTOK, 128>>>(x, ln1_g, ln1_b, xh, xl);
    // 3. QKV GEMM -> fp32 qkv
    mma_gemm<0><<<dim3(12, NTOK / 128), 256, gemm_smem>>>(
        xh, xl, wq_h, wq_l, qkv_b, nullptr, qkv, nullptr, nullptr, 512, 1536);
    // 4. local attention (tensor cores) -> bf16 hi/lo
    attn_mma_kernel<<<dim3(NW, HEADS, B_), 128, attn_smem>>>(qkv, ah, al);
    // 5. proj + residual(x) -> fp32 y
    mma_gemm<1><<<dim3(4, NTOK / 128), 256, gemm_smem>>>(
        ah, al, wp_h, wp_l, proj_b, x, y, nullptr, nullptr, 512, 512);
    // 6. LN2 -> bf16 hi/lo
    ln_kernel<0><<<NTOK, 128>>>(y, ln2_g, ln2_b, xh, xl);
    // 7. MLP up + GELU -> bf16 hi/lo
    mma_gemm<2><<<dim3(16, NTOK / 128), 256, gemm_smem>>>(
        xh, xl, w1_h, w1_l, mlp_b1, nullptr, nullptr, fh, fl, 512, 2048);
    // 8. MLP down + residual(y) -> out
    mma_gemm<1><<<dim3(4, NTOK / 128), 256, gemm_smem>>>(
        fh, fl, w2_h, w2_l, mlp_b2, y, out, nullptr, nullptr, 2048, 512);
}

// round 9
// speedup vs baseline: 1.6243x; 1.4619x over previous
#include <cuda_runtime.h>
#include <cuda_bf16.h>
#include <cuda_fp16.h>
#include <math.h>
#include <cstdint>

#define B_    8
#define SEQ   8192
#define DIM   512
#define HEADS 8
#define HD    64
#define FF_   2048
#define WIN   128
#define TD    512
#define NTOK  (B_*SEQ)        // 65536
#define NW    (SEQ/WIN)       // 64

// ---------------- scratch (device globals; no runtime allocation) ----------
__device__ float g_ss  [B_ * 2 * DIM];
__device__ float g_qkv [(size_t)NTOK * 3 * DIM];   // fp32 qkv
__device__ float g_y   [(size_t)NTOK * DIM];       // x + proj(attn), fp32
// single-fp16 activations (GEMM A operands)
__device__ __half g_xf [(size_t)NTOK * DIM];       // LN1 / LN2 out
__device__ __half g_af [(size_t)NTOK * DIM];       // attention out
__device__ __half g_ff [(size_t)NTOK * FF_];       // gelu out
// weights hi/lo fp16, transposed to [N][K] (K contiguous)
__device__ __half g_wq_h[1536 * 512],  g_wq_l[1536 * 512];
__device__ __half g_wp_h[512 * 512],   g_wp_l[512 * 512];
__device__ __half g_w1_h[2048 * 512],  g_w1_l[2048 * 512];
__device__ __half g_w2_h[512 * 2048],  g_w2_l[512 * 2048];

// ---------------- PTX helpers ----------------------------------------------
__device__ __forceinline__ uint32_t smem_u32(const void* p) {
    uint32_t a;
    asm("{ .reg .u64 t; cvta.to.shared.u64 t, %1; cvt.u32.u64 %0, t; }"
        : "=r"(a) : "l"(p));
    return a;
}
__device__ __forceinline__ void cp16(uint32_t dst, const void* src) {
    asm volatile("cp.async.cg.shared.global [%0], [%1], 16;"
                 :: "r"(dst), "l"(src) : "memory");
}
#define CP_COMMIT() asm volatile("cp.async.commit_group;" ::: "memory")
#define CP_WAIT(n)  asm volatile("cp.async.wait_group %0;" :: "n"(n) : "memory")

__device__ __forceinline__ void ldsm4(uint32_t* r, uint32_t addr) {
    asm volatile("ldmatrix.sync.aligned.m8n8.x4.shared.b16 {%0,%1,%2,%3}, [%4];"
                 : "=r"(r[0]), "=r"(r[1]), "=r"(r[2]), "=r"(r[3]) : "r"(addr));
}
__device__ __forceinline__ void ldsm4t(uint32_t* r, uint32_t addr) {
    asm volatile("ldmatrix.sync.aligned.m8n8.x4.trans.shared.b16 {%0,%1,%2,%3}, [%4];"
                 : "=r"(r[0]), "=r"(r[1]), "=r"(r[2]), "=r"(r[3]) : "r"(addr));
}
// bf16 mma (attention)
__device__ __forceinline__ void mma_bf(float* d, const uint32_t* a,
                                       const uint32_t* b) {
    asm volatile(
        "mma.sync.aligned.m16n8k16.row.col.f32.bf16.bf16.f32 "
        "{%0,%1,%2,%3}, {%4,%5,%6,%7}, {%8,%9}, {%0,%1,%2,%3};"
        : "+f"(d[0]), "+f"(d[1]), "+f"(d[2]), "+f"(d[3])
        : "r"(a[0]), "r"(a[1]), "r"(a[2]), "r"(a[3]), "r"(b[0]), "r"(b[1]));
}
// fp16 mma (GEMMs)
__device__ __forceinline__ void mma_fp(float* d, const uint32_t* a,
                                       const uint32_t* b) {
    asm volatile(
        "mma.sync.aligned.m16n8k16.row.col.f32.f16.f16.f32 "
        "{%0,%1,%2,%3}, {%4,%5,%6,%7}, {%8,%9}, {%0,%1,%2,%3};"
        : "+f"(d[0]), "+f"(d[1]), "+f"(d[2]), "+f"(d[3])
        : "r"(a[0]), "r"(a[1]), "r"(a[2]), "r"(a[3]), "r"(b[0]), "r"(b[1]));
}
__device__ __forceinline__ uint32_t swz(uint32_t r, uint32_t c16) {
    return (r << 7) + ((c16 ^ (r & 7)) << 4);
}
__device__ __forceinline__ void split_hl_bf(float v, __nv_bfloat16& h, __nv_bfloat16& l) {
    h = __float2bfloat16(v);
    l = __float2bfloat16(v - __bfloat162float(h));
}
__device__ __forceinline__ uint32_t pack_bf2(__nv_bfloat16 a, __nv_bfloat16 b) {
    __nv_bfloat162 p = __halves2bfloat162(a, b);
    return *reinterpret_cast<uint32_t*>(&p);
}
__device__ __forceinline__ uint32_t pack_h2(float a, float b) {
    __half2 p = __floats2half2_rn(a, b);
    return *reinterpret_cast<uint32_t*>(&p);
}

// ---------------- kernel 0: weight transpose + fp16 hi/lo split ------------
__global__ void wprep_kernel(const float* __restrict__ W,
                             __half* __restrict__ oh,
                             __half* __restrict__ ol, int K, int N) {
    __shared__ float tile[32][33];
    int bx = blockIdx.x * 32, by = blockIdx.y * 32;
    int tx = threadIdx.x, ty = threadIdx.y;
    #pragma unroll
    for (int i = 0; i < 4; i++) {
        int k = by + ty + i * 8;
        tile[ty + i * 8][tx] = W[(size_t)k * N + bx + tx];
    }
    __syncthreads();
    #pragma unroll
    for (int i = 0; i < 4; i++) {
        int n = bx + ty + i * 8;
        int k = by + tx;
        float v = tile[tx][ty + i * 8];
        __half h = __float2half_rn(v);
        __half l = __float2half_rn(v - __half2float(h));
        oh[(size_t)n * K + k] = h;
        ol[(size_t)n * K + k] = l;
    }
}

// ---------------- kernel 1: ss = silu(t_emb) @ time_w + time_b -------------
__global__ void time_mlp_kernel(const float* __restrict__ te,
                                const float* __restrict__ tw,
                                const float* __restrict__ tb) {
    __shared__ float st[TD];
    int b = blockIdx.y;
    for (int k = threadIdx.x; k < TD; k += blockDim.x) {
        float v = te[b * TD + k];
        st[k] = v / (1.f + __expf(-v));
    }
    __syncthreads();
    int j = blockIdx.x * blockDim.x + threadIdx.x;
    float acc = tb[j];
    for (int k = 0; k < TD; k++)
        acc = fmaf(st[k], tw[k * (2 * DIM) + j], acc);
    g_ss[b * 2 * DIM + j] = acc;
}

// ---------------- kernel 2: LayerNorm -> single fp16 -----------------------
template <int MOD>
__global__ void ln_kernel(const float* __restrict__ x,
                          const float* __restrict__ gam,
                          const float* __restrict__ bet,
                          __half* __restrict__ of) {
    int row  = blockIdx.x;
    int t    = threadIdx.x;
    int lane = t & 31, wid = t >> 5;
    float4 xv = ((const float4*)(x + (size_t)row * DIM))[t];
    float s  = xv.x + xv.y + xv.z + xv.w;
    float s2 = fmaf(xv.x, xv.x, fmaf(xv.y, xv.y, fmaf(xv.z, xv.z, xv.w * xv.w)));
    #pragma unroll
    for (int o = 16; o > 0; o >>= 1) {
        s  += __shfl_xor_sync(0xffffffffu, s,  o);
        s2 += __shfl_xor_sync(0xffffffffu, s2, o);
    }
    __shared__ float red[8];
    if (lane == 0) { red[wid] = s; red[4 + wid] = s2; }
    __syncthreads();
    s  = red[0] + red[1] + red[2] + red[3];
    s2 = red[4] + red[5] + red[6] + red[7];
    float mu   = s * (1.f / DIM);
    float var  = s2 * (1.f / DIM) - mu * mu;
    float rstd = rsqrtf(var + 1e-5f);

    float4 gg = ((const float4*)gam)[t];
    float4 bb = ((const float4*)bet)[t];
    float o4[4];
    o4[0] = (xv.x - mu) * rstd * gg.x + bb.x;
    o4[1] = (xv.y - mu) * rstd * gg.y + bb.y;
    o4[2] = (xv.z - mu) * rstd * gg.z + bb.z;
    o4[3] = (xv.w - mu) * rstd * gg.w + bb.w;
    if (MOD) {
        int b = row >> 13;
        float4 sc = ((const float4*)(g_ss + b * 2 * DIM))[t];
        float4 sh = ((const float4*)(g_ss + b * 2 * DIM + DIM))[t];
        o4[0] = o4[0] * (1.f + sc.x) + sh.x;
        o4[1] = o4[1] * (1.f + sc.y) + sh.y;
        o4[2] = o4[2] * (1.f + sc.z) + sh.z;
        o4[3] = o4[3] * (1.f + sc.w) + sh.w;
    }
    ((uint2*)(of + (size_t)row * DIM))[t] =
        make_uint2(pack_h2(o4[0], o4[1]), pack_h2(o4[2], o4[3]));
}

// ---------------- kernel 3: fp16 2-term GEMM, K-tile 64, 2-stage -----------
// C[M,N] = A[M,K] @ (Bh+Bl)[N,K]^T + bias [...]
// A single fp16; B fp16 hi/lo (≈ exact fp32 weights). 2 MMAs per k16.
// EPI: 0 = bias -> f32; 1 = bias+res -> f32; 2 = bias+GELU -> fp16
#define KSTEP 64
#define STG   49152
template <int EPI>
__global__ __launch_bounds__(256, 2)
void mma_gemm(const __half* __restrict__ A,
              const __half* __restrict__ Bh,
              const __half* __restrict__ Bl,
              const float* __restrict__ bias,
              const float* __restrict__ res,
              float* __restrict__ Cf,
              __half* __restrict__ Ch,
              int K, int N) {
    extern __shared__ char smem[];
    const uint32_t sbase = smem_u32(smem);
    const int tid = threadIdx.x, w = tid >> 5, lane = tid & 31;
    const int bm = blockIdx.y * 128, bn = blockIdx.x * 128;
    const int warpM = (w >> 2) * 64, warpN = (w & 3) * 32;
    const int T = K / KSTEP;

    const int r_ld = tid >> 3, c_ld = tid & 7;

    auto issue = [&](int t) {
        int k0 = t * KSTEP;
        uint32_t sa  = sbase + (t & 1) * STG;
        uint32_t sbh = sa + 16384;
        uint32_t sbl = sa + 32768;
        #pragma unroll
        for (int i = 0; i < 4; i++) {
            int r = r_ld + i * 32;
            uint32_t off = swz((uint32_t)r, (uint32_t)c_ld);
            cp16(sa  + off, A  + (size_t)(bm + r) * K + k0 + c_ld * 8);
            cp16(sbh + off, Bh + (size_t)(bn + r) * K + k0 + c_ld * 8);
            cp16(sbl + off, Bl + (size_t)(bn + r) * K + k0 + c_ld * 8);
        }
        CP_COMMIT();
    };

    float acc[4][4][4];
    #pragma unroll
    for (int i = 0; i < 4; i++)
        #pragma unroll
        for (int j = 0; j < 4; j++)
            #pragma unroll
            for (int e = 0; e < 4; e++) acc[i][j][e] = 0.f;

    const int laA_r = lane & 15, laA_h = lane >> 4;
    const int laB_r = (lane & 7) + ((lane >> 4) << 3);
    const int laB_h = (lane >> 3) & 1;

    issue(0);
    for (int t = 0; t < T; t++) {
        if (t + 1 < T) { issue(t + 1); CP_WAIT(1); }
        else           { CP_WAIT(0); }
        __syncthreads();

        uint32_t sa  = sbase + (t & 1) * STG;
        uint32_t sbh = sa + 16384;
        uint32_t sbl = sa + 32768;
        #pragma unroll
        for (int i = 0; i < 4; i++) {        // k16 groups within 64-K tile
            uint32_t af[4][4], bfh[2][4], bfl[2][4];
            #pragma unroll
            for (int mi = 0; mi < 4; mi++) {
                uint32_t row = warpM + mi * 16 + laA_r;
                ldsm4(af[mi], sa + swz(row, 2 * i + laA_h));
            }
            #pragma unroll
            for (int nj = 0; nj < 2; nj++) {
                uint32_t row = warpN + nj * 16 + laB_r;
                ldsm4(bfh[nj], sbh + swz(row, 2 * i + laB_h));
                ldsm4(bfl[nj], sbl + swz(row, 2 * i + laB_h));
            }
            #pragma unroll
            for (int mi = 0; mi < 4; mi++)
                #pragma unroll
                for (int n8 = 0; n8 < 4; n8++) {
                    mma_fp(acc[mi][n8], af[mi], &bfh[n8 >> 1][(n8 & 1) * 2]);
                    mma_fp(acc[mi][n8], af[mi], &bfl[n8 >> 1][(n8 & 1) * 2]);
                }
        }
        __syncthreads();
    }

    int tr = lane >> 2, tc = (lane & 3) * 2;
    #pragma unroll
    for (int mi = 0; mi < 4; mi++) {
        #pragma unroll
        for (int half = 0; half < 2; half++) {
            int row = bm + warpM + mi * 16 + tr + half * 8;
            size_t rowoff = (size_t)row * N;
            #pragma unroll
            for (int n8 = 0; n8 < 4; n8++) {
                int col = bn + warpN + n8 * 8 + tc;
                float2 bi = *(const float2*)(bias + col);
                float ox = acc[mi][n8][half * 2 + 0] + bi.x;
                float oy = acc[mi][n8][half * 2 + 1] + bi.y;
                if (EPI == 1) {
                    float2 rr = *(const float2*)(res + rowoff + col);
                    ox += rr.x; oy += rr.y;
                }
                if (EPI == 2) {
                    ox = 0.5f * ox * (1.f + erff(ox * 0.70710678118654752f));
                    oy = 0.5f * oy * (1.f + erff(oy * 0.70710678118654752f));
                    *(uint32_t*)(Ch + rowoff + col) = pack_h2(ox, oy);
                } else {
                    *(float2*)(Cf + rowoff + col) = make_float2(ox, oy);
                }
            }
        }
    }
}

// ---------------- kernel 4: local windowed attention via mma.sync ----------
// bf16 3-term internally (reads fp32 qkv); outputs single fp16.
__global__ __launch_bounds__(128)
void attn_mma_kernel(const float* __restrict__ qkv,
                     __half* __restrict__ of) {
    extern __shared__ char smc[];
    const uint32_t sQh = smem_u32(smc);
    const uint32_t sQl = sQh + 16384;
    const uint32_t sKh = sQh + 32768;
    const uint32_t sKl = sQh + 49152;
    const uint32_t sVh = sQh + 65536;
    const uint32_t sVl = sQh + 81920;

    const int w = blockIdx.x, h = blockIdx.y, b = blockIdx.z;
    const int tid = threadIdx.x, lane = tid & 31;
    const int warpM = (tid >> 5) * 32;

    const int laA_r = lane & 15, laA_h = lane >> 4;
    const int laB_r = (lane & 7) + ((lane >> 4) << 3);
    const int laB_h = (lane >> 3) & 1;

    // ---- load Q (x 0.125) -> hi/lo smem (thread = query row) ----
    {
        const float* qp = qkv + (size_t)(b * SEQ + w * WIN + tid) * (3 * DIM) + h * HD;
        #pragma unroll
        for (int c = 0; c < 8; c++) {
            float4 v0 = ((const float4*)qp)[c * 2];
            float4 v1 = ((const float4*)qp)[c * 2 + 1];
            float f[8] = {v0.x, v0.y, v0.z, v0.w, v1.x, v1.y, v1.z, v1.w};
            uint32_t hp[4], lp[4];
            #pragma unroll
            for (int e = 0; e < 4; e++) {
                __nv_bfloat16 h0, l0, h1, l1;
                split_hl_bf(f[2 * e] * 0.125f, h0, l0);
                split_hl_bf(f[2 * e + 1] * 0.125f, h1, l1);
                hp[e] = pack_bf2(h0, h1);
                lp[e] = pack_bf2(l0, l1);
            }
            uint32_t off = swz((uint32_t)tid, (uint32_t)c);
            *(uint4*)(smc + off)         = make_uint4(hp[0], hp[1], hp[2], hp[3]);
            *(uint4*)(smc + 16384 + off) = make_uint4(lp[0], lp[1], lp[2], lp[3]);
        }
    }

    float O[2][8][4];
    #pragma unroll
    for (int mt = 0; mt < 2; mt++)
        #pragma unroll
        for (int n8 = 0; n8 < 8; n8++)
            #pragma unroll
            for (int e = 0; e < 4; e++) O[mt][n8][e] = 0.f;
    float mS[2][2] = {{-1e30f, -1e30f}, {-1e30f, -1e30f}};
    float lS[2][2] = {{0.f, 0.f}, {0.f, 0.f}};

    for (int dw = -1; dw <= 1; dw++) {
        int wi = w + dw;
        if (wi < 0 || wi >= NW) continue;
        __syncthreads();
        // ---- load K,V window -> hi/lo smem (thread = key row) ----
        {
            const float* kp = qkv + (size_t)(b * SEQ + wi * WIN + tid) * (3 * DIM) + DIM + h * HD;
            const float* vp = kp + DIM;
            #pragma unroll
            for (int c = 0; c < 8; c++) {
                float4 k0 = ((const float4*)kp)[c * 2];
                float4 k1 = ((const float4*)kp)[c * 2 + 1];
                float4 u0 = ((const float4*)vp)[c * 2];
                float4 u1 = ((const float4*)vp)[c * 2 + 1];
                float fk[8] = {k0.x, k0.y, k0.z, k0.w, k1.x, k1.y, k1.z, k1.w};
                float fv[8] = {u0.x, u0.y, u0.z, u0.w, u1.x, u1.y, u1.z, u1.w};
                uint32_t kh[4], kl[4], vh[4], vl[4];
                #pragma unroll
                for (int e = 0; e < 4; e++) {
                    __nv_bfloat16 a0, b0, a1, b1;
                    split_hl_bf(fk[2 * e], a0, b0); split_hl_bf(fk[2 * e + 1], a1, b1);
                    kh[e] = pack_bf2(a0, a1); kl[e] = pack_bf2(b0, b1);
                    split_hl_bf(fv[2 * e], a0, b0); split_hl_bf(fv[2 * e + 1], a1, b1);
                    vh[e] = pack_bf2(a0, a1); vl[e] = pack_bf2(b0, b1);
                }
                uint32_t off = swz((uint32_t)tid, (uint32_t)c);
                *(uint4*)(smc + 32768 + off) = make_uint4(kh[0], kh[1], kh[2], kh[3]);
                *(uint4*)(smc + 49152 + off) = make_uint4(kl[0], kl[1], kl[2], kl[3]);
                *(uint4*)(smc + 65536 + off) = make_uint4(vh[0], vh[1], vh[2], vh[3]);
                *(uint4*)(smc + 81920 + off) = make_uint4(vl[0], vl[1], vl[2], vl[3]);
            }
        }
        __syncthreads();

        #pragma unroll
        for (int c0 = 0; c0 < 128; c0 += 64) {
            float S[2][8][4];
            #pragma unroll
            for (int mt = 0; mt < 2; mt++)
                #pragma unroll
                for (int n8 = 0; n8 < 8; n8++)
                    #pragma unroll
                    for (int e = 0; e < 4; e++) S[mt][n8][e] = 0.f;

            #pragma unroll
            for (int kb = 0; kb < 4; kb++) {
                uint32_t aqh[2][4], aql[2][4], bkh[4][4], bkl[4][4];
                #pragma unroll
                for (int mt = 0; mt < 2; mt++) {
                    uint32_t row = warpM + mt * 16 + laA_r;
                    ldsm4(aqh[mt], sQh + swz(row, kb * 2 + laA_h));
                    ldsm4(aql[mt], sQl + swz(row, kb * 2 + laA_h));
                }
                #pragma unroll
                for (int np = 0; np < 4; np++) {
                    uint32_t row = c0 + np * 16 + laB_r;
                    ldsm4(bkh[np], sKh + swz(row, kb * 2 + laB_h));
                    ldsm4(bkl[np], sKl + swz(row, kb * 2 + laB_h));
                }
                #pragma unroll
                for (int mt = 0; mt < 2; mt++)
                    #pragma unroll
                    for (int n8 = 0; n8 < 8; n8++) {
                        const uint32_t* bh2 = &bkh[n8 >> 1][(n8 & 1) * 2];
                        const uint32_t* bl2 = &bkl[n8 >> 1][(n8 & 1) * 2];
                        mma_bf(S[mt][n8], aqh[mt], bh2);
                        mma_bf(S[mt][n8], aqh[mt], bl2);
                        mma_bf(S[mt][n8], aql[mt], bh2);
                    }
            }

            #pragma unroll
            for (int mt = 0; mt < 2; mt++) {
                #pragma unroll
                for (int half = 0; half < 2; half++) {
                    float cm = -1e30f;
                    #pragma unroll
                    for (int n8 = 0; n8 < 8; n8++) {
                        cm = fmaxf(cm, S[mt][n8][half * 2 + 0]);
                        cm = fmaxf(cm, S[mt][n8][half * 2 + 1]);
                    }
                    cm = fmaxf(cm, __shfl_xor_sync(0xffffffffu, cm, 1));
                    cm = fmaxf(cm, __shfl_xor_sync(0xffffffffu, cm, 2));
                    float mn = fmaxf(mS[mt][half], cm);
                    float corr = __expf(mS[mt][half] - mn);
                    float rs = 0.f;
                    #pragma unroll
                    for (int n8 = 0; n8 < 8; n8++) {
                        float p0 = __expf(S[mt][n8][half * 2 + 0] - mn);
                        float p1 = __expf(S[mt][n8][half * 2 + 1] - mn);
                        S[mt][n8][half * 2 + 0] = p0;
                        S[mt][n8][half * 2 + 1] = p1;
                        rs += p0 + p1;
                    }
                    rs += __shfl_xor_sync(0xffffffffu, rs, 1);
                    rs += __shfl_xor_sync(0xffffffffu, rs, 2);
                    lS[mt][half] = lS[mt][half] * corr + rs;
                    mS[mt][half] = mn;
                    #pragma unroll
                    for (int n8 = 0; n8 < 8; n8++) {
                        O[mt][n8][half * 2 + 0] *= corr;
                        O[mt][n8][half * 2 + 1] *= corr;
                    }
                }
            }

            #pragma unroll
            for (int kb = 0; kb < 4; kb++) {
                uint32_t ph[2][4], pl[2][4];
                #pragma unroll
                for (int mt = 0; mt < 2; mt++) {
                    #pragma unroll
                    for (int i = 0; i < 4; i++) {
                        int j = 2 * kb + (i >> 1);
                        float p0 = S[mt][j][(i & 1) * 2 + 0];
                        float p1 = S[mt][j][(i & 1) * 2 + 1];
                        __nv_bfloat16 h0 = __float2bfloat16(p0);
                        __nv_bfloat16 h1 = __float2bfloat16(p1);
                        ph[mt][i] = pack_bf2(h0, h1);
                        pl[mt][i] = pack_bf2(
                            __float2bfloat16(p0 - __bfloat162float(h0)),
                            __float2bfloat16(p1 - __bfloat162float(h1)));
                    }
                }
                uint32_t vfh[4][4], vfl[4][4];
                #pragma unroll
                for (int np = 0; np < 4; np++) {
                    uint32_t row = c0 + kb * 16 + (lane & 15);
                    uint32_t ch = np * 2 + (lane >> 4);
                    ldsm4t(vfh[np], sVh + swz(row, ch));
                    ldsm4t(vfl[np], sVl + swz(row, ch));
                }
                #pragma unroll
                for (int mt = 0; mt < 2; mt++)
                    #pragma unroll
                    for (int n8 = 0; n8 < 8; n8++) {
                        const uint32_t* vh2 = &vfh[n8 >> 1][(n8 & 1) * 2];
                        const uint32_t* vl2 = &vfl[n8 >> 1][(n8 & 1) * 2];
                        mma_bf(O[mt][n8], ph[mt], vh2);
                        mma_bf(O[mt][n8], ph[mt], vl2);
                        mma_bf(O[mt][n8], pl[mt], vh2);
                    }
            }
        }
    }

    #pragma unroll
    for (int mt = 0; mt < 2; mt++) {
        #pragma unroll
        for (int half = 0; half < 2; half++) {
            float inv = 1.f / lS[mt][half];
            int row = warpM + mt * 16 + (lane >> 2) + half * 8;
            size_t base = (size_t)(b * SEQ + w * WIN + row) * DIM + h * HD;
            #pragma unroll
            for (int n8 = 0; n8 < 8; n8++) {
                int col = n8 * 8 + (lane & 3) * 2;
                float x0 = O[mt][n8][half * 2 + 0] * inv;
                float x1 = O[mt][n8][half * 2 + 1] * inv;
                *(uint32_t*)(of + base + col) = pack_h2(x0, x1);
            }
        }
    }
}

// ---------------- host orchestration ---------------------------------------
extern "C" void kernel_launch(void* const* d_in, const int* in_sizes, int n_in,
                              void* d_out, int out_size) {
    const float* x      = (const float*)d_in[0];
    const float* t_emb  = (const float*)d_in[1];
    const float* ln1_g  = (const float*)d_in[2];
    const float* ln1_b  = (const float*)d_in[3];
    const float* qkv_w  = (const float*)d_in[4];
    const float* qkv_b  = (const float*)d_in[5];
    const float* proj_w = (const float*)d_in[6];
    const float* proj_b = (const float*)d_in[7];
    const float* ln2_g  = (const float*)d_in[8];
    const float* ln2_b  = (const float*)d_in[9];
    const float* mlp_w1 = (const float*)d_in[10];
    const float* mlp_b1 = (const float*)d_in[11];
    const float* mlp_w2 = (const float*)d_in[12];
    const float* mlp_b2 = (const float*)d_in[13];
    const float* time_w = (const float*)d_in[14];
    const float* time_b = (const float*)d_in[15];
    float* out = (float*)d_out;

    void* p;
    float *qkv, *y;
    __half *xf, *af, *ff;
    __half *wq_h, *wq_l, *wp_h, *wp_l, *w1_h, *w1_l, *w2_h, *w2_l;
    cudaGetSymbolAddress(&p, g_qkv);  qkv = (float*)p;
    cudaGetSymbolAddress(&p, g_y);    y   = (float*)p;
    cudaGetSymbolAddress(&p, g_xf);   xf  = (__half*)p;
    cudaGetSymbolAddress(&p, g_af);   af  = (__half*)p;
    cudaGetSymbolAddress(&p, g_ff);   ff  = (__half*)p;
    cudaGetSymbolAddress(&p, g_wq_h); wq_h = (__half*)p;
    cudaGetSymbolAddress(&p, g_wq_l); wq_l = (__half*)p;
    cudaGetSymbolAddress(&p, g_wp_h); wp_h = (__half*)p;
    cudaGetSymbolAddress(&p, g_wp_l); wp_l = (__half*)p;
    cudaGetSymbolAddress(&p, g_w1_h); w1_h = (__half*)p;
    cudaGetSymbolAddress(&p, g_w1_l); w1_l = (__half*)p;
    cudaGetSymbolAddress(&p, g_w2_h); w2_h = (__half*)p;
    cudaGetSymbolAddress(&p, g_w2_l); w2_l = (__half*)p;

    const int gemm_smem = 2 * STG;   // 96 KB
    cudaFuncSetAttribute(mma_gemm<0>, cudaFuncAttributeMaxDynamicSharedMemorySize, gemm_smem);
    cudaFuncSetAttribute(mma_gemm<1>, cudaFuncAttributeMaxDynamicSharedMemorySize, gemm_smem);
    cudaFuncSetAttribute(mma_gemm<2>, cudaFuncAttributeMaxDynamicSharedMemorySize, gemm_smem);
    const int attn_smem = 98304;
    cudaFuncSetAttribute(attn_mma_kernel, cudaFuncAttributeMaxDynamicSharedMemorySize, attn_smem);

    // 0. weight prep (transpose + fp16 hi/lo split)
    wprep_kernel<<<dim3(1536 / 32, 512 / 32), dim3(32, 8)>>>(qkv_w,  wq_h, wq_l, 512, 1536);
    wprep_kernel<<<dim3(512 / 32,  512 / 32), dim3(32, 8)>>>(proj_w, wp_h, wp_l, 512, 512);
    wprep_kernel<<<dim3(2048 / 32, 512 / 32), dim3(32, 8)>>>(mlp_w1, w1_h, w1_l, 512, 2048);
    wprep_kernel<<<dim3(512 / 32, 2048 / 32), dim3(32, 8)>>>(mlp_w2, w2_h, w2_l, 2048, 512);
    // 1. adaLN scale/shift
    time_mlp_kernel<<<dim3(2 * DIM / 256, B_), 256>>>(t_emb, time_w, time_b);
    // 2. modulated LN1 -> fp16
    ln_kernel<1><<<NTOK, 128>>>(x, ln1_g, ln1_b, xf);
    // 3. QKV GEMM -> fp32 qkv
    mma_gemm<0><<<dim3(12, NTOK / 128), 256, gemm_smem>>>(
        xf, wq_h, wq_l, qkv_b, nullptr, qkv, nullptr, 512, 1536);
    // 4. local attention -> fp16
    attn_mma_kernel<<<dim3(NW, HEADS, B_), 128, attn_smem>>>(qkv, af);
    // 5. proj + residual(x) -> fp32 y
    mma_gemm<1><<<dim3(4, NTOK / 128), 256, gemm_smem>>>(
        af, wp_h, wp_l, proj_b, x, y, nullptr, 512, 512);
    // 6. LN2 -> fp16
    ln_kernel<0><<<NTOK, 128>>>(y, ln2_g, ln2_b, xf);
    // 7. MLP up + GELU -> fp16
    mma_gemm<2><<<dim3(16, NTOK / 128), 256, gemm_smem>>>(
        xf, w1_h, w1_l, mlp_b1, nullptr, nullptr, ff, 512, 2048);
    // 8. MLP down + residual(y) -> out
    mma_gemm<1><<<dim3(4, NTOK / 128), 256, gemm_smem>>>(
        ff, w2_h, w2_l, mlp_b2, y, out, nullptr, 2048, 512);
}